// round 3
// baseline (speedup 1.0000x reference)
#include <cuda_runtime.h>
#include <cuda_bf16.h>

__device__ int g_is_cyclic;

__global__ void check_cyclic_kernel(const int* __restrict__ mul, int n) {
    __shared__ int ok;
    if (threadIdx.x == 0) ok = 1;
    __syncthreads();
    int total = n * n;
    for (int i = threadIdx.x; i < total; i += blockDim.x) {
        int a = i / n;
        int b = i - a * n;
        int e = a + b;
        if (e >= n) e -= n;
        if (__ldg(mul + i) != e) ok = 0;   // benign race: all writers store 0
    }
    __syncthreads();
    if (threadIdx.x == 0) g_is_cyclic = ok;
}

#define TPB 256  // 8 warps per block

// Persistent: grid sized to one resident wave; each warp grid-strides over rows.
__global__ void __launch_bounds__(TPB, 8) a5_scan_kernel(
    const float* __restrict__ scale_p,
    const int* __restrict__ ids,
    const int* __restrict__ mul,
    float* __restrict__ out,
    int n, int b_rows, int t_len, int total_warps)
{
    int lane  = threadIdx.x & 31;
    int warp0 = (int)((blockIdx.x * (unsigned)TPB + threadIdx.x) >> 5);
    bool cyclic = (g_is_cyclic != 0);

    float sc = __ldg(scale_p);
    float hi = 10.0f * sc;
    float lo = -10.0f * sc;

    int nvec = t_len >> 2;
    bool vec_ok = ((t_len & 3) == 0);

    for (int r = warp0; r < b_rows; r += total_warps) {
        const int* row = ids + (long long)r * t_len;
        int s;

        if (cyclic && vec_ok) {
            // s = (sum of row) % n  — R1-proven loop body
            const int4* rowv = (const int4*)row;
            int sum = 0;
            #pragma unroll 8
            for (int j = lane; j < nvec; j += 32) {
                int4 v = __ldg(rowv + j);       // coalesced 512B per warp step
                sum += v.x + v.y + v.z + v.w;
            }
            #pragma unroll
            for (int d = 16; d; d >>= 1)
                sum += __shfl_xor_sync(0xffffffffu, sum, d);
            s = sum % n;
        } else if ((t_len & 31) == 0) {
            // General ordered group product fallback
            int chunk = t_len >> 5;
            const int* base = row + lane * chunk;
            int q = 0;                          // identity
            for (int j = 0; j < chunk; j++) {
                int x = __ldg(base + j);
                q = __ldg(mul + x * n + q);     // q = x . q
            }
            #pragma unroll
            for (int d = 1; d < 32; d <<= 1) {
                int t = __shfl_up_sync(0xffffffffu, q, d);
                if (lane >= d) q = __ldg(mul + q * n + t);
            }
            s = __shfl_sync(0xffffffffu, q, 31);
        } else {
            int q = 0;
            if (lane == 0)
                for (int j = 0; j < t_len; j++)
                    q = __ldg(mul + __ldg(row + j) * n + q);
            s = __shfl_sync(0xffffffffu, q, 0);
        }

        float* orow = out + (long long)r * n;
        for (int i = lane; i < n; i += 32)
            orow[i] = (i == s) ? hi : lo;
    }
}

extern "C" void kernel_launch(void* const* d_in, const int* in_sizes, int n_in,
                              void* d_out, int out_size) {
    const float* scale = (const float*)d_in[0];
    const int*   ids   = (const int*)d_in[1];
    const int*   mul   = (const int*)d_in[2];
    float*       out   = (float*)d_out;

    int mn = in_sizes[2];
    int n = 1;
    while (n * n < mn) n++;

    int b_rows = out_size / n;              // 8192
    int t_len  = in_sizes[1] / b_rows;      // 2048

    check_cyclic_kernel<<<1, 256>>>(mul, n);

    // Size the grid to exactly one resident wave (host queries: capture-safe,
    // not stream ops, and only executed at capture/correctness time).
    int dev = 0, sms = 148;
    cudaGetDevice(&dev);
    cudaDeviceGetAttribute(&sms, cudaDevAttrMultiProcessorCount, dev);
    int blocks_per_sm = 0;
    cudaOccupancyMaxActiveBlocksPerMultiprocessor(&blocks_per_sm,
                                                  a5_scan_kernel, TPB, 0);
    if (blocks_per_sm < 1) blocks_per_sm = 1;

    int max_blocks = (b_rows * 32 + TPB - 1) / TPB;   // never exceed 1 warp/row
    int blocks = sms * blocks_per_sm;
    if (blocks > max_blocks) blocks = max_blocks;
    int total_warps = blocks * (TPB / 32);

    a5_scan_kernel<<<blocks, TPB>>>(scale, ids, mul, out,
                                    n, b_rows, t_len, total_warps);
}

// round 4
// speedup vs baseline: 1.1197x; 1.1197x over previous
#include <cuda_runtime.h>
#include <cuda_bf16.h>

__device__ int g_is_cyclic;

// 1 block x 1024 threads: 4 independent loads per thread -> ~0.4us node.
__global__ void __launch_bounds__(1024) check_cyclic_kernel(
    const int* __restrict__ mul, int n)
{
    __shared__ int ok;
    if (threadIdx.x == 0) ok = 1;
    __syncthreads();
    int total = n * n;
    for (int i = threadIdx.x; i < total; i += 1024) {
        int a = i / n;
        int b = i - a * n;
        int e = a + b;
        if (e >= n) e -= n;
        if (__ldg(mul + i) != e) ok = 0;   // benign race: all writers store 0
    }
    __syncthreads();
    if (threadIdx.x == 0) g_is_cyclic = ok;
}

#define TPB 256  // 8 warps per block

// Each warp owns TWO rows (r, r + total_warps), loads interleaved so both
// rows' LDG.128s are in flight together. Grid = one balanced wave.
__global__ void __launch_bounds__(TPB) a5_scan_kernel(
    const float* __restrict__ scale_p,
    const int* __restrict__ ids,
    const int* __restrict__ mul,
    float* __restrict__ out,
    int n, int b_rows, int t_len, int total_warps)
{
    int lane  = threadIdx.x & 31;
    int warp0 = (int)((blockIdx.x * (unsigned)TPB + threadIdx.x) >> 5);
    bool cyclic = (g_is_cyclic != 0);

    float sc = __ldg(scale_p);
    float hi = 10.0f * sc;
    float lo = -10.0f * sc;

    int nvec = t_len >> 2;
    bool vec_ok = ((t_len & 3) == 0);

    for (int r = warp0; r < b_rows; r += 2 * total_warps) {
        int r2 = r + total_warps;
        bool have2 = (r2 < b_rows);

        if (cyclic && vec_ok) {
            const int4* p0 = (const int4*)(ids + (long long)r * t_len);
            const int4* p1 = (const int4*)(ids + (long long)(have2 ? r2 : r) * t_len);
            int s0 = 0, s1 = 0;
            #pragma unroll 4
            for (int j = lane; j < nvec; j += 32) {
                int4 a = __ldg(p0 + j);
                int4 b = __ldg(p1 + j);
                s0 += a.x + a.y + a.z + a.w;
                s1 += b.x + b.y + b.z + b.w;
            }
            #pragma unroll
            for (int d = 16; d; d >>= 1) {
                s0 += __shfl_xor_sync(0xffffffffu, s0, d);
                s1 += __shfl_xor_sync(0xffffffffu, s1, d);
            }
            int sa = s0 % n;
            int sb = s1 % n;

            float* o0 = out + (long long)r * n;
            for (int i = lane; i < n; i += 32)
                o0[i] = (i == sa) ? hi : lo;
            if (have2) {
                float* o1 = out + (long long)r2 * n;
                for (int i = lane; i < n; i += 32)
                    o1[i] = (i == sb) ? hi : lo;
            }
        } else {
            // General ordered group product fallback (per row)
            for (int k = 0; k < 2; k++) {
                int rr = (k == 0) ? r : r2;
                if (k == 1 && !have2) break;
                const int* row = ids + (long long)rr * t_len;
                int s;
                if ((t_len & 31) == 0) {
                    int chunk = t_len >> 5;
                    const int* base = row + lane * chunk;
                    int q = 0;                       // identity
                    for (int j = 0; j < chunk; j++) {
                        int x = __ldg(base + j);
                        q = __ldg(mul + x * n + q);  // q = x . q
                    }
                    #pragma unroll
                    for (int d = 1; d < 32; d <<= 1) {
                        int t = __shfl_up_sync(0xffffffffu, q, d);
                        if (lane >= d) q = __ldg(mul + q * n + t);
                    }
                    s = __shfl_sync(0xffffffffu, q, 31);
                } else {
                    int q = 0;
                    if (lane == 0)
                        for (int j = 0; j < t_len; j++)
                            q = __ldg(mul + __ldg(row + j) * n + q);
                    s = __shfl_sync(0xffffffffu, q, 0);
                }
                float* orow = out + (long long)rr * n;
                for (int i = lane; i < n; i += 32)
                    orow[i] = (i == s) ? hi : lo;
            }
        }
    }
}

extern "C" void kernel_launch(void* const* d_in, const int* in_sizes, int n_in,
                              void* d_out, int out_size) {
    const float* scale = (const float*)d_in[0];
    const int*   ids   = (const int*)d_in[1];
    const int*   mul   = (const int*)d_in[2];
    float*       out   = (float*)d_out;

    int mn = in_sizes[2];
    int n = 1;
    while (n * n < mn) n++;

    int b_rows = out_size / n;              // 8192
    int t_len  = in_sizes[1] / b_rows;      // 2048

    check_cyclic_kernel<<<1, 1024>>>(mul, n);

    // 2 rows per warp -> 16 rows per 8-warp block -> 512 blocks (one wave).
    const int warps_per_block = TPB / 32;
    int blocks = (b_rows + 2 * warps_per_block - 1) / (2 * warps_per_block);
    int total_warps = blocks * warps_per_block;

    a5_scan_kernel<<<blocks, TPB>>>(scale, ids, mul, out,
                                    n, b_rows, t_len, total_warps);
}